// round 1
// baseline (speedup 1.0000x reference)
#include <cuda_runtime.h>

// Problem constants (fixed by reference setup_inputs)
#define D_MODEL 1024
#define HEAD    64      // HEAD_SIZE
#define NHEAD   16
#define ROWS    16384   // B*S = 4*4096
#define NGRP    1024    // ROWS/NHEAD

// Scratch (device globals — no allocation allowed)
__device__ __align__(128) float g_qp[ROWS * HEAD];
__device__ __align__(128) float g_kp[ROWS * HEAD];
__device__ __align__(128) float g_vp[ROWS * HEAD];
__device__ __align__(128) float g_x [NGRP * D_MODEL];

// ---------------------------------------------------------------------------
// Generic row-major GEMM + bias: C[M,N] = A[M,K] @ B[K,N] + bias[N]
// BM=128, BN=64, BK=32, 256 threads, per-thread 8x4 register tile.
// Requires M%128==0, N%64==0, K%32==0 (true for all uses here).
// ---------------------------------------------------------------------------
__global__ __launch_bounds__(256)
void gemm_bias_kernel(const float* __restrict__ A, const float* __restrict__ B,
                      const float* __restrict__ bias, float* __restrict__ C,
                      int M, int N, int K)
{
    const int BK = 32;
    __shared__ float As[128][33];   // +1 pad: conflict-free stores & 2-row broadcast reads
    __shared__ float Bs[32][64];

    const int tid = threadIdx.x;
    const int bm  = blockIdx.x * 128;
    const int bn  = blockIdx.y * 64;
    const int tx  = tid & 15;    // 16 col groups x 4 cols
    const int ty  = tid >> 4;    // 16 row groups x 8 rows

    float acc[8][4];
#pragma unroll
    for (int m = 0; m < 8; m++)
#pragma unroll
        for (int n = 0; n < 4; n++) acc[m][n] = 0.f;

    const int arow = tid >> 3;          // 0..31
    const int acol = (tid & 7) * 4;     // 0..28
    const int brow = tid >> 4;          // 0..15
    const int bcol = (tid & 15) * 4;    // 0..60

    for (int k0 = 0; k0 < K; k0 += BK) {
        // Load A tile 128x32 (float4 along K, coalesced)
#pragma unroll
        for (int i = 0; i < 4; i++) {
            float4 v = *(const float4*)&A[(size_t)(bm + arow + i * 32) * K + k0 + acol];
            As[arow + i * 32][acol + 0] = v.x;
            As[arow + i * 32][acol + 1] = v.y;
            As[arow + i * 32][acol + 2] = v.z;
            As[arow + i * 32][acol + 3] = v.w;
        }
        // Load B tile 32x64 (float4 along N, coalesced)
#pragma unroll
        for (int i = 0; i < 2; i++) {
            float4 v = *(const float4*)&B[(size_t)(k0 + brow + i * 16) * N + bn + bcol];
            *(float4*)&Bs[brow + i * 16][bcol] = v;
        }
        __syncthreads();

#pragma unroll
        for (int k = 0; k < BK; k++) {
            float4 bv = *(const float4*)&Bs[k][tx * 4];
            float b0 = bv.x, b1 = bv.y, b2 = bv.z, b3 = bv.w;
#pragma unroll
            for (int m = 0; m < 8; m++) {
                float a = As[ty * 8 + m][k];
                acc[m][0] += a * b0;
                acc[m][1] += a * b1;
                acc[m][2] += a * b2;
                acc[m][3] += a * b3;
            }
        }
        __syncthreads();
    }

#pragma unroll
    for (int m = 0; m < 8; m++) {
        const int row = bm + ty * 8 + m;
#pragma unroll
        for (int n = 0; n < 4; n++) {
            const int col = bn + tx * 4 + n;
            C[(size_t)row * N + col] = acc[m][n] + bias[col];
        }
    }
}

// ---------------------------------------------------------------------------
// Attention middle stage. One CTA per group n (1024 groups), 128 threads.
//   scores[i][j] = 0.25 * sum_hh Qp[16n+hh, i] * Kp[16n+hh, j]   (masked)
//   X[n, h*64 + i] = sum_j scores[i][j] * Vp[16n+h, j]
// ---------------------------------------------------------------------------
__global__ __launch_bounds__(128)
void attn_kernel(const float* __restrict__ qp, const float* __restrict__ kp,
                 const float* __restrict__ vp, const int* __restrict__ mask,
                 float* __restrict__ X)
{
    const int n   = blockIdx.x;
    const int tid = threadIdx.x;

    __shared__ float Qs[16][65];
    __shared__ float Ks[16][65];
    __shared__ float Vs[16][65];
    __shared__ float S [64][65];

    const float* qg = qp + (size_t)n * NHEAD * HEAD;
    const float* kg = kp + (size_t)n * NHEAD * HEAD;
    const float* vg = vp + (size_t)n * NHEAD * HEAD;

#pragma unroll
    for (int idx = tid; idx < NHEAD * HEAD; idx += 128) {
        int r = idx >> 6, c = idx & 63;
        Qs[r][c] = qg[idx];
        Ks[r][c] = kg[idx];
        Vs[r][c] = vg[idx];
    }
    __syncthreads();

    // scores (64x64), 32 entries per thread
#pragma unroll
    for (int idx = tid; idx < 64 * 64; idx += 128) {
        int i = idx >> 6, j = idx & 63;
        float s = 0.f;
#pragma unroll
        for (int hh = 0; hh < 16; hh++) s += Qs[hh][i] * Ks[hh][j];
        s *= 0.25f;                        // scale = 16^-0.5
        if (mask[i * 64 + j] == 0) s = -1e30f;
        S[i][j] = s;
    }
    __syncthreads();

    // X[n, h*64+i] = sum_j S[i][j] * Vs[h][j], 8 entries per thread
#pragma unroll
    for (int idx = tid; idx < 64 * 16; idx += 128) {
        int i = idx >> 4, h = idx & 15;
        float acc = 0.f;
#pragma unroll
        for (int j = 0; j < 64; j++) acc += S[i][j] * Vs[h][j];
        X[(size_t)n * D_MODEL + h * HEAD + i] = acc;
    }
}

// ---------------------------------------------------------------------------
extern "C" void kernel_launch(void* const* d_in, const int* in_sizes, int n_in,
                              void* d_out, int out_size)
{
    const float* query = (const float*)d_in[0];
    const float* key   = (const float*)d_in[1];
    const float* value = (const float*)d_in[2];
    const int*   mask  = (const int*)  d_in[3];
    const float* Wq    = (const float*)d_in[4];
    const float* bq    = (const float*)d_in[5];
    const float* Wk    = (const float*)d_in[6];
    const float* bk    = (const float*)d_in[7];
    const float* Wv    = (const float*)d_in[8];
    const float* bv    = (const float*)d_in[9];
    const float* Wp    = (const float*)d_in[10];
    const float* bp    = (const float*)d_in[11];
    float* out = (float*)d_out;

    float *qp, *kp, *vp, *xg;
    cudaGetSymbolAddress((void**)&qp, g_qp);
    cudaGetSymbolAddress((void**)&kp, g_kp);
    cudaGetSymbolAddress((void**)&vp, g_vp);
    cudaGetSymbolAddress((void**)&xg, g_x);

    dim3 blk(256);

    // Projections: (16384 x 1024) @ (1024 x 64) + bias
    gemm_bias_kernel<<<dim3(ROWS / 128, 1), blk>>>(query, Wq, bq, qp, ROWS, HEAD, D_MODEL);
    gemm_bias_kernel<<<dim3(ROWS / 128, 1), blk>>>(key,   Wk, bk, kp, ROWS, HEAD, D_MODEL);
    gemm_bias_kernel<<<dim3(ROWS / 128, 1), blk>>>(value, Wv, bv, vp, ROWS, HEAD, D_MODEL);

    // Attention middle stage -> X (1024 x 1024)
    attn_kernel<<<NGRP, 128>>>(qp, kp, vp, mask, xg);

    // Output projection: (1024 x 1024) @ (1024 x 1024) + bias
    gemm_bias_kernel<<<dim3(NGRP / 128, D_MODEL / 64), blk>>>(xg, Wp, bp, out,
                                                              NGRP, D_MODEL, D_MODEL);
}

// round 3
// speedup vs baseline: 1.1954x; 1.1954x over previous
#include <cuda_runtime.h>
#include <cuda_bf16.h>
#include <cstdint>

// Problem constants (fixed by reference setup_inputs)
#define D_MODEL 1024
#define HEAD    64
#define NHEAD   16
#define ROWS    16384   // B*S
#define NGRP    1024    // ROWS/NHEAD

// ---------------------------------------------------------------------------
// Scratch (device globals — no allocation allowed)
// ---------------------------------------------------------------------------
__device__ __align__(128) float g_qp[ROWS * HEAD];
__device__ __align__(128) float g_kp[ROWS * HEAD];
__device__ __align__(128) float g_vp[ROWS * HEAD];
__device__ __align__(128) float g_x [NGRP * D_MODEL];

// Pre-transposed + bf16-split weights: layout [N, K] (K-major rows)
__device__ __align__(128) __nv_bfloat16 g_wq_h[HEAD * D_MODEL];
__device__ __align__(128) __nv_bfloat16 g_wq_l[HEAD * D_MODEL];
__device__ __align__(128) __nv_bfloat16 g_wk_h[HEAD * D_MODEL];
__device__ __align__(128) __nv_bfloat16 g_wk_l[HEAD * D_MODEL];
__device__ __align__(128) __nv_bfloat16 g_wv_h[HEAD * D_MODEL];
__device__ __align__(128) __nv_bfloat16 g_wv_l[HEAD * D_MODEL];
__device__ __align__(128) __nv_bfloat16 g_wp_h[D_MODEL * D_MODEL];
__device__ __align__(128) __nv_bfloat16 g_wp_l[D_MODEL * D_MODEL];

// ---------------------------------------------------------------------------
// mma.sync m16n8k16 bf16 (baseline PTX, no sm_103a-only features)
// ---------------------------------------------------------------------------
__device__ __forceinline__ void mma_bf16(float* d, const uint32_t* a, const uint32_t* b) {
    asm volatile(
        "mma.sync.aligned.m16n8k16.row.col.f32.bf16.bf16.f32 "
        "{%0,%1,%2,%3}, {%4,%5,%6,%7}, {%8,%9}, {%0,%1,%2,%3};\n"
        : "+f"(d[0]), "+f"(d[1]), "+f"(d[2]), "+f"(d[3])
        : "r"(a[0]), "r"(a[1]), "r"(a[2]), "r"(a[3]), "r"(b[0]), "r"(b[1]));
}

__device__ __forceinline__ void bf16_split2(float x, float y, uint32_t& hi, uint32_t& lo) {
    __nv_bfloat16 hx = __float2bfloat16(x);
    __nv_bfloat16 hy = __float2bfloat16(y);
    float rx = x - __bfloat162float(hx);
    float ry = y - __bfloat162float(hy);
    __nv_bfloat162 h; h.x = hx; h.y = hy;
    __nv_bfloat162 l; l.x = __float2bfloat16(rx); l.y = __float2bfloat16(ry);
    hi = *reinterpret_cast<uint32_t*>(&h);
    lo = *reinterpret_cast<uint32_t*>(&l);
}

// ---------------------------------------------------------------------------
// Weight prep: W[K,N] fp32 -> Wt_hi/Wt_lo [N,K] bf16 (transpose + split)
// ---------------------------------------------------------------------------
__global__ void prep_split_kernel(const float* __restrict__ W,
                                  __nv_bfloat16* __restrict__ Th,
                                  __nv_bfloat16* __restrict__ Tl,
                                  int N /* cols of W */)
{
    int idx = blockIdx.x * 256 + threadIdx.x;      // idx over N*K, K = 1024
    int n = idx >> 10;
    int k = idx & 1023;
    if (n >= N) return;
    float x = W[k * N + n];
    __nv_bfloat16 h = __float2bfloat16(x);
    Th[idx] = h;
    Tl[idx] = __float2bfloat16(x - __bfloat162float(h));
}

// ---------------------------------------------------------------------------
// Tensor-core GEMM via mma.sync: C[M,N] = A[M,1024] @ Bt^T + bias
//   A fp32 row-major (lda = 1024), Bt hi/lo bf16 [N, 1024] K-major.
//   2-term bf16 split: D = Ah*Bh + Ah*Bl + Al*Bh
// BM=128, BN=64, BK=64, 256 threads = 8 warps (4 M x 2 N), warp tile 32x32.
// ---------------------------------------------------------------------------
#define PADK 72        // 64 + 8 bf16 pad -> 144-byte row stride (conflict-free)
#define SM_AH_OFF 0
#define SM_AL_OFF (128 * PADK)
#define SM_BH_OFF (2 * 128 * PADK)
#define SM_BL_OFF (2 * 128 * PADK + 64 * PADK)
#define SM_ELEMS  (2 * 128 * PADK + 2 * 64 * PADK)
#define SM_BYTES  (SM_ELEMS * 2)   // 55296

__global__ __launch_bounds__(256)
void gemm_tc_kernel(const float* __restrict__ A,
                    const __nv_bfloat16* __restrict__ Bth,
                    const __nv_bfloat16* __restrict__ Btl,
                    const float* __restrict__ bias,
                    float* __restrict__ C, int ldc)
{
    extern __shared__ __nv_bfloat16 sm[];
    __nv_bfloat16* AH = sm + SM_AH_OFF;
    __nv_bfloat16* AL = sm + SM_AL_OFF;
    __nv_bfloat16* BH = sm + SM_BH_OFF;
    __nv_bfloat16* BL = sm + SM_BL_OFF;

    const int tid  = threadIdx.x;
    const int w    = tid >> 5, lane = tid & 31;
    const int g    = lane >> 2, t = lane & 3;
    const int wm   = (w >> 1) * 32;     // warp M origin in tile
    const int wn   = (w & 1) * 32;      // warp N origin in tile
    const int bm   = blockIdx.x * 128;
    const int bn   = blockIdx.y * 64;

    float acc[2][4][4];
#pragma unroll
    for (int mt = 0; mt < 2; mt++)
#pragma unroll
        for (int nt = 0; nt < 4; nt++)
#pragma unroll
            for (int r = 0; r < 4; r++) acc[mt][nt][r] = 0.f;

    for (int ch = 0; ch < 16; ch++) {
        const int k0 = ch * 64;

        // ---- prefetch gmem into regs (overlaps previous chunk's MMAs)
        float4 aR[8];
#pragma unroll
        for (int p = 0; p < 8; p++) {
            int idx = p * 256 + tid;
            int r = idx >> 4, c4 = idx & 15;
            aR[p] = *(const float4*)&A[(size_t)(bm + r) * 1024 + k0 + c4 * 4];
        }
        uint4 bhR[2], blR[2];
#pragma unroll
        for (int p = 0; p < 2; p++) {
            int idx = p * 256 + tid;
            int r = idx >> 3, c8 = idx & 7;
            size_t off = (size_t)(bn + r) * 1024 + k0 + c8 * 8;
            bhR[p] = *(const uint4*)(Bth + off);
            blR[p] = *(const uint4*)(Btl + off);
        }

        __syncthreads();   // previous chunk fully consumed

        // ---- split A to bf16 hi/lo, store tiles
#pragma unroll
        for (int p = 0; p < 8; p++) {
            int idx = p * 256 + tid;
            int r = idx >> 4, c4 = idx & 15;
            uint32_t h01, l01, h23, l23;
            bf16_split2(aR[p].x, aR[p].y, h01, l01);
            bf16_split2(aR[p].z, aR[p].w, h23, l23);
            *(uint2*)(AH + r * PADK + c4 * 4) = make_uint2(h01, h23);
            *(uint2*)(AL + r * PADK + c4 * 4) = make_uint2(l01, l23);
        }
#pragma unroll
        for (int p = 0; p < 2; p++) {
            int idx = p * 256 + tid;
            int r = idx >> 3, c8 = idx & 7;
            *(uint4*)(BH + r * PADK + c8 * 8) = bhR[p];
            *(uint4*)(BL + r * PADK + c8 * 8) = blR[p];
        }
        __syncthreads();

        // ---- 4 k16-steps of MMAs
#pragma unroll
        for (int ks = 0; ks < 4; ks++) {
            const int kk = ks * 16;
            uint32_t ah[2][4], al[2][4], bh[4][2], bl[4][2];
#pragma unroll
            for (int mt = 0; mt < 2; mt++) {
                const __nv_bfloat16* ph = AH + (wm + mt * 16 + g) * PADK + kk + t * 2;
                const __nv_bfloat16* pl = AL + (wm + mt * 16 + g) * PADK + kk + t * 2;
                ah[mt][0] = *(const uint32_t*)(ph);
                ah[mt][1] = *(const uint32_t*)(ph + 8 * PADK);
                ah[mt][2] = *(const uint32_t*)(ph + 8);
                ah[mt][3] = *(const uint32_t*)(ph + 8 * PADK + 8);
                al[mt][0] = *(const uint32_t*)(pl);
                al[mt][1] = *(const uint32_t*)(pl + 8 * PADK);
                al[mt][2] = *(const uint32_t*)(pl + 8);
                al[mt][3] = *(const uint32_t*)(pl + 8 * PADK + 8);
            }
#pragma unroll
            for (int nt = 0; nt < 4; nt++) {
                const __nv_bfloat16* ph = BH + (wn + nt * 8 + g) * PADK + kk + t * 2;
                const __nv_bfloat16* pl = BL + (wn + nt * 8 + g) * PADK + kk + t * 2;
                bh[nt][0] = *(const uint32_t*)(ph);
                bh[nt][1] = *(const uint32_t*)(ph + 8);
                bl[nt][0] = *(const uint32_t*)(pl);
                bl[nt][1] = *(const uint32_t*)(pl + 8);
            }
#pragma unroll
            for (int mt = 0; mt < 2; mt++)
#pragma unroll
                for (int nt = 0; nt < 4; nt++) {
                    mma_bf16(acc[mt][nt], ah[mt], bh[nt]);
                    mma_bf16(acc[mt][nt], ah[mt], bl[nt]);
                    mma_bf16(acc[mt][nt], al[mt], bh[nt]);
                }
        }
    }

    // ---- epilogue: bias + store (c0,c1 -> row, c2,c3 -> row+8)
#pragma unroll
    for (int mt = 0; mt < 2; mt++) {
        const int row0 = bm + wm + mt * 16 + g;
#pragma unroll
        for (int nt = 0; nt < 4; nt++) {
            const int col = bn + wn + nt * 8 + t * 2;
            const float b0 = __ldg(&bias[col]);
            const float b1 = __ldg(&bias[col + 1]);
            float2 v0 = make_float2(acc[mt][nt][0] + b0, acc[mt][nt][1] + b1);
            float2 v1 = make_float2(acc[mt][nt][2] + b0, acc[mt][nt][3] + b1);
            *(float2*)&C[(size_t)row0 * ldc + col]       = v0;
            *(float2*)&C[(size_t)(row0 + 8) * ldc + col] = v1;
        }
    }
}

// ---------------------------------------------------------------------------
// Attention middle stage (register-tiled). One CTA per group n, 128 threads.
//   S[i][j] = 0.25 * sum_hh Qp[16n+hh, i] * Kp[16n+hh, j]   (masked)
//   X[n, h*64 + i] = sum_j S[i][j] * Vp[16n+h, j]
// ---------------------------------------------------------------------------
__global__ __launch_bounds__(128)
void attn_kernel(const float* __restrict__ qp, const float* __restrict__ kp,
                 const float* __restrict__ vp, const int* __restrict__ mask,
                 float* __restrict__ X)
{
    __shared__ float Qs[16 * 64];
    __shared__ float Ks[16 * 64];
    __shared__ float Vs[16 * 64];
    __shared__ float S [64 * 64];

    const int n = blockIdx.x, tid = threadIdx.x;
    const float4* qg = (const float4*)(qp + (size_t)n * NHEAD * HEAD);
    const float4* kg = (const float4*)(kp + (size_t)n * NHEAD * HEAD);
    const float4* vg = (const float4*)(vp + (size_t)n * NHEAD * HEAD);
    float4* Qs4 = (float4*)Qs;
    float4* Ks4 = (float4*)Ks;
    float4* Vs4 = (float4*)Vs;

#pragma unroll
    for (int t = tid; t < 256; t += 128) {
        Qs4[t] = qg[t];
        Ks4[t] = kg[t];
        Vs4[t] = vg[t];
    }
    __syncthreads();

    // Stage 1: S = 0.25 * Q^T K (per-thread 4x8 tile)
    const int ti = tid >> 3, tj = tid & 7;   // i0 = ti*4, j0 = tj*8
    float acc[4][8];
#pragma unroll
    for (int r = 0; r < 4; r++)
#pragma unroll
        for (int c = 0; c < 8; c++) acc[r][c] = 0.f;

#pragma unroll
    for (int hh = 0; hh < 16; hh++) {
        float4 q  = Qs4[hh * 16 + ti];
        float4 ka = Ks4[hh * 16 + tj * 2];
        float4 kb = Ks4[hh * 16 + tj * 2 + 1];
        float qv[4] = {q.x, q.y, q.z, q.w};
        float kv[8] = {ka.x, ka.y, ka.z, ka.w, kb.x, kb.y, kb.z, kb.w};
#pragma unroll
        for (int r = 0; r < 4; r++)
#pragma unroll
            for (int c = 0; c < 8; c++) acc[r][c] += qv[r] * kv[c];
    }
#pragma unroll
    for (int r = 0; r < 4; r++) {
        int i = ti * 4 + r;
#pragma unroll
        for (int c = 0; c < 8; c++) {
            int j = tj * 8 + c;
            float s = acc[r][c] * 0.25f;
            if (__ldg(&mask[i * 64 + j]) == 0) s = -1e30f;
            S[i * 64 + j] = s;
        }
    }
    __syncthreads();

    // Stage 2: X[i, h] = S[i,:] . V[h,:]  (per-thread 4i x 2h tile)
    const int a = tid >> 3, b = tid & 7;    // i0 = a*4, h0 = b*2
    const float4* S4 = (const float4*)S;
    float acc2[4][2];
#pragma unroll
    for (int r = 0; r < 4; r++) { acc2[r][0] = 0.f; acc2[r][1] = 0.f; }

#pragma unroll
    for (int j4 = 0; j4 < 16; j4++) {
        float4 v0 = Vs4[(b * 2 + 0) * 16 + j4];
        float4 v1 = Vs4[(b * 2 + 1) * 16 + j4];
#pragma unroll
        for (int r = 0; r < 4; r++) {
            float4 sv = S4[(a * 4 + r) * 16 + j4];
            acc2[r][0] += sv.x * v0.x + sv.y * v0.y + sv.z * v0.z + sv.w * v0.w;
            acc2[r][1] += sv.x * v1.x + sv.y * v1.y + sv.z * v1.z + sv.w * v1.w;
        }
    }

    float* Xn = X + (size_t)n * D_MODEL;
#pragma unroll
    for (int r = 0; r < 4; r++) {
#pragma unroll
        for (int c = 0; c < 2; c++) {
            Xn[(b * 2 + c) * 64 + a * 4 + r] = acc2[r][c];
        }
    }
}

// ---------------------------------------------------------------------------
extern "C" void kernel_launch(void* const* d_in, const int* in_sizes, int n_in,
                              void* d_out, int out_size)
{
    const float* query = (const float*)d_in[0];
    const float* key   = (const float*)d_in[1];
    const float* value = (const float*)d_in[2];
    const int*   mask  = (const int*)  d_in[3];
    const float* Wq    = (const float*)d_in[4];
    const float* bq    = (const float*)d_in[5];
    const float* Wk    = (const float*)d_in[6];
    const float* bk    = (const float*)d_in[7];
    const float* Wv    = (const float*)d_in[8];
    const float* bv    = (const float*)d_in[9];
    const float* Wp    = (const float*)d_in[10];
    const float* bp    = (const float*)d_in[11];
    float* out = (float*)d_out;

    float *qp, *kp, *vp, *xg;
    cudaGetSymbolAddress((void**)&qp, g_qp);
    cudaGetSymbolAddress((void**)&kp, g_kp);
    cudaGetSymbolAddress((void**)&vp, g_vp);
    cudaGetSymbolAddress((void**)&xg, g_x);
    __nv_bfloat16 *wqh, *wql, *wkh, *wkl, *wvh, *wvl, *wph, *wpl;
    cudaGetSymbolAddress((void**)&wqh, g_wq_h);
    cudaGetSymbolAddress((void**)&wql, g_wq_l);
    cudaGetSymbolAddress((void**)&wkh, g_wk_h);
    cudaGetSymbolAddress((void**)&wkl, g_wk_l);
    cudaGetSymbolAddress((void**)&wvh, g_wv_h);
    cudaGetSymbolAddress((void**)&wvl, g_wv_l);
    cudaGetSymbolAddress((void**)&wph, g_wp_h);
    cudaGetSymbolAddress((void**)&wpl, g_wp_l);

    static bool attr_done = false;
    if (!attr_done) {
        cudaFuncSetAttribute(gemm_tc_kernel,
                             cudaFuncAttributeMaxDynamicSharedMemorySize, SM_BYTES);
        attr_done = true;
    }

    // Weight prep (transpose + bf16 split)
    prep_split_kernel<<<(HEAD * D_MODEL) / 256, 256>>>(Wq, wqh, wql, HEAD);
    prep_split_kernel<<<(HEAD * D_MODEL) / 256, 256>>>(Wk, wkh, wkl, HEAD);
    prep_split_kernel<<<(HEAD * D_MODEL) / 256, 256>>>(Wv, wvh, wvl, HEAD);
    prep_split_kernel<<<(D_MODEL * D_MODEL) / 256, 256>>>(Wp, wph, wpl, D_MODEL);

    // Projections: (16384 x 1024) @ (1024 x 64) + bias
    gemm_tc_kernel<<<dim3(ROWS / 128, 1), 256, SM_BYTES>>>(query, wqh, wql, bq, qp, HEAD);
    gemm_tc_kernel<<<dim3(ROWS / 128, 1), 256, SM_BYTES>>>(key,   wkh, wkl, bk, kp, HEAD);
    gemm_tc_kernel<<<dim3(ROWS / 128, 1), 256, SM_BYTES>>>(value, wvh, wvl, bv, vp, HEAD);

    // Attention middle stage -> X (1024 x 1024)
    attn_kernel<<<NGRP, 128>>>(qp, kp, vp, mask, xg);

    // Output projection: (1024 x 1024) @ (1024 x 1024) + bias
    gemm_tc_kernel<<<dim3(NGRP / 128, D_MODEL / 64), 256, SM_BYTES>>>(xg, wph, wpl, bp, out, D_MODEL);
}

// round 4
// speedup vs baseline: 1.3690x; 1.1452x over previous
#include <cuda_runtime.h>
#include <cuda_bf16.h>
#include <cstdint>

// Problem constants (fixed by reference setup_inputs)
#define D_MODEL 1024
#define HEAD    64
#define NHEAD   16
#define ROWS    16384   // B*S
#define NGRP    1024    // ROWS/NHEAD

// ---------------------------------------------------------------------------
// Scratch (device globals — no allocation allowed)
// ---------------------------------------------------------------------------
__device__ __align__(128) float g_qp[ROWS * HEAD];
__device__ __align__(128) float g_kp[ROWS * HEAD];
__device__ __align__(128) float g_vp[ROWS * HEAD];
__device__ __align__(128) float g_x [NGRP * D_MODEL];

// Pre-transposed + bf16-split weights: layout [N, K] (K-major rows)
__device__ __align__(128) __nv_bfloat16 g_wq_h[HEAD * D_MODEL];
__device__ __align__(128) __nv_bfloat16 g_wq_l[HEAD * D_MODEL];
__device__ __align__(128) __nv_bfloat16 g_wk_h[HEAD * D_MODEL];
__device__ __align__(128) __nv_bfloat16 g_wk_l[HEAD * D_MODEL];
__device__ __align__(128) __nv_bfloat16 g_wv_h[HEAD * D_MODEL];
__device__ __align__(128) __nv_bfloat16 g_wv_l[HEAD * D_MODEL];
__device__ __align__(128) __nv_bfloat16 g_wp_h[D_MODEL * D_MODEL];
__device__ __align__(128) __nv_bfloat16 g_wp_l[D_MODEL * D_MODEL];

// ---------------------------------------------------------------------------
// PTX helpers (baseline features only: sm_80-era, safe for compute_103 target)
// ---------------------------------------------------------------------------
__device__ __forceinline__ uint32_t smem_u32(const void* p) {
    uint32_t a;
    asm("{ .reg .u64 t; cvta.to.shared.u64 t, %1; cvt.u32.u64 %0, t; }" : "=r"(a) : "l"(p));
    return a;
}
__device__ __forceinline__ void mma_bf16(float* d, const uint32_t* a, const uint32_t* b) {
    asm volatile(
        "mma.sync.aligned.m16n8k16.row.col.f32.bf16.bf16.f32 "
        "{%0,%1,%2,%3}, {%4,%5,%6,%7}, {%8,%9}, {%0,%1,%2,%3};\n"
        : "+f"(d[0]), "+f"(d[1]), "+f"(d[2]), "+f"(d[3])
        : "r"(a[0]), "r"(a[1]), "r"(a[2]), "r"(a[3]), "r"(b[0]), "r"(b[1]));
}
__device__ __forceinline__ void ldsm_x4(uint32_t* r, uint32_t addr) {
    asm volatile("ldmatrix.sync.aligned.m8n8.x4.shared.b16 {%0,%1,%2,%3}, [%4];"
                 : "=r"(r[0]), "=r"(r[1]), "=r"(r[2]), "=r"(r[3]) : "r"(addr));
}
__device__ __forceinline__ void cp_async16(uint32_t dst, const void* src) {
    asm volatile("cp.async.cg.shared.global [%0], [%1], 16;" :: "r"(dst), "l"(src));
}
#define CP_COMMIT() asm volatile("cp.async.commit_group;")
#define CP_WAIT0()  asm volatile("cp.async.wait_group 0;" ::: "memory")

__device__ __forceinline__ void bf16_split2(float x, float y, uint32_t& hi, uint32_t& lo) {
    __nv_bfloat16 hx = __float2bfloat16(x);
    __nv_bfloat16 hy = __float2bfloat16(y);
    float rx = x - __bfloat162float(hx);
    float ry = y - __bfloat162float(hy);
    __nv_bfloat162 h; h.x = hx; h.y = hy;
    __nv_bfloat162 l; l.x = __float2bfloat16(rx); l.y = __float2bfloat16(ry);
    hi = *reinterpret_cast<uint32_t*>(&h);
    lo = *reinterpret_cast<uint32_t*>(&l);
}

// ---------------------------------------------------------------------------
// Weight prep: W[K,N] fp32 -> Wt_hi/Wt_lo [N,K] bf16 (smem-tiled transpose+split)
// Block (32,8) handles a 32(k) x 32(n) tile. Coalesced reads & writes.
// ---------------------------------------------------------------------------
__global__ __launch_bounds__(256)
void prep_tr_split_kernel(const float* __restrict__ W,
                          __nv_bfloat16* __restrict__ Th,
                          __nv_bfloat16* __restrict__ Tl, int N)
{
    __shared__ float t[32][33];
    const int n0 = blockIdx.x * 32, k0 = blockIdx.y * 32;
    const int tx = threadIdx.x, ty = threadIdx.y;
#pragma unroll
    for (int j = 0; j < 4; j++)
        t[ty + 8 * j][tx] = W[(size_t)(k0 + ty + 8 * j) * N + n0 + tx];
    __syncthreads();
#pragma unroll
    for (int j = 0; j < 4; j++) {
        float x = t[tx][ty + 8 * j];            // = W[k0+tx][n0+ty+8j]
        __nv_bfloat16 h = __float2bfloat16(x);
        size_t o = (size_t)(n0 + ty + 8 * j) * 1024 + k0 + tx;
        Th[o] = h;
        Tl[o] = __float2bfloat16(x - __bfloat162float(h));
    }
}

// ---------------------------------------------------------------------------
// Tensor-core GEMM body: C[bm:+128, bn:+64] = A[.,1024] @ Bt^T + bias
//   A fp32 row-major (lda=1024), Bt hi/lo bf16 [N,1024] K-major.
//   2-term bf16 split: D = Ah*Bh + Ah*Bl + Al*Bh
// BM=128, BN=64, BK=64, 256 threads = 8 warps (4M x 2N), warp tile 32x32.
// Double-buffered SMEM, cp.async for B, register-prefetched A, ldmatrix frags.
// ---------------------------------------------------------------------------
#define PADK 72                         // bf16 elems per smem row (144 B)
#define OFF_AH 0
#define OFF_AL (128 * PADK)
#define OFF_BH (2 * 128 * PADK)
#define OFF_BL (2 * 128 * PADK + 64 * PADK)
#define STAGE_ELEMS (2 * 128 * PADK + 2 * 64 * PADK)   // 27648
#define SM_BYTES (2 * STAGE_ELEMS * 2)                 // 110592

__device__ __forceinline__
void gemm_body(const float* __restrict__ A,
               const __nv_bfloat16* __restrict__ Bth,
               const __nv_bfloat16* __restrict__ Btl,
               const float* __restrict__ bias,
               float* __restrict__ C, int ldc,
               int bm, int bn, __nv_bfloat16* sm)
{
    const uint32_t sb = smem_u32(sm);
    const int tid  = threadIdx.x;
    const int lane = tid & 31, w = tid >> 5;
    const int g = lane >> 2, t = lane & 3;
    const int wm = (w >> 1) * 32, wn = (w & 1) * 32;

    // ldmatrix lane addressing components
    const int rowA  = (lane & 15);              // 0..15 within 16-row block
    const int colA8 = (lane >> 4) * 8;          // k half select
    const int rowB  = ((lane >> 4) & 1) * 8 + (lane & 7);   // n within 16-row pair
    const int colB8 = ((lane >> 3) & 1) * 8;    // k half select

    // per-thread load mappings
    const int ar = tid >> 1;                    // A row pair base helper (idx>>4 later)
    (void)ar;

    float acc[2][4][4];
#pragma unroll
    for (int mt = 0; mt < 2; mt++)
#pragma unroll
        for (int nt = 0; nt < 4; nt++)
#pragma unroll
            for (int r = 0; r < 4; r++) acc[mt][nt][r] = 0.f;

    float4 aR[8];

    // ---------------- helpers as lambdas ----------------
    auto load_A_regs = [&](int ch) {
        const int k0 = ch * 64;
#pragma unroll
        for (int p = 0; p < 8; p++) {
            int idx = p * 256 + tid;
            int r = idx >> 4, c4 = idx & 15;
            aR[p] = *(const float4*)&A[(size_t)(bm + r) * 1024 + k0 + c4 * 4];
        }
    };
    auto store_A = [&](int stg) {
        __nv_bfloat16* AH = sm + stg * STAGE_ELEMS + OFF_AH;
        __nv_bfloat16* AL = sm + stg * STAGE_ELEMS + OFF_AL;
#pragma unroll
        for (int p = 0; p < 8; p++) {
            int idx = p * 256 + tid;
            int r = idx >> 4, c4 = idx & 15;
            uint32_t h01, l01, h23, l23;
            bf16_split2(aR[p].x, aR[p].y, h01, l01);
            bf16_split2(aR[p].z, aR[p].w, h23, l23);
            *(uint2*)(AH + r * PADK + c4 * 4) = make_uint2(h01, h23);
            *(uint2*)(AL + r * PADK + c4 * 4) = make_uint2(l01, l23);
        }
    };
    auto cp_B = [&](int ch, int stg) {
        const int k0 = ch * 64;
        const uint32_t bh = sb + (stg * STAGE_ELEMS + OFF_BH) * 2;
        const uint32_t bl = sb + (stg * STAGE_ELEMS + OFF_BL) * 2;
#pragma unroll
        for (int p = 0; p < 2; p++) {
            int idx = p * 256 + tid;
            int r = idx >> 3, c8 = idx & 7;
            size_t off = (size_t)(bn + r) * 1024 + k0 + c8 * 8;
            uint32_t d = (uint32_t)(r * 144 + c8 * 16);
            cp_async16(bh + d, Bth + off);
            cp_async16(bl + d, Btl + off);
        }
        CP_COMMIT();
    };
    auto do_mma = [&](int stg) {
        const uint32_t base = sb + (stg * STAGE_ELEMS) * 2;
        const uint32_t ahB = base + OFF_AH * 2;
        const uint32_t alB = base + OFF_AL * 2;
        const uint32_t bhB = base + OFF_BH * 2;
        const uint32_t blB = base + OFF_BL * 2;
#pragma unroll
        for (int ks = 0; ks < 4; ks++) {
            const int kk = ks * 16;
            uint32_t ah[2][4], al[2][4], bh[4][2], bl[4][2];
#pragma unroll
            for (int mt = 0; mt < 2; mt++) {
                uint32_t off = (uint32_t)((wm + mt * 16 + rowA) * 144 + (kk + colA8) * 2);
                ldsm_x4(ah[mt], ahB + off);
                ldsm_x4(al[mt], alB + off);
            }
#pragma unroll
            for (int p = 0; p < 2; p++) {
                uint32_t off = (uint32_t)((wn + p * 16 + rowB) * 144 + (kk + colB8) * 2);
                uint32_t rh[4], rl[4];
                ldsm_x4(rh, bhB + off);
                ldsm_x4(rl, blB + off);
                bh[2 * p][0] = rh[0]; bh[2 * p][1] = rh[1];
                bh[2 * p + 1][0] = rh[2]; bh[2 * p + 1][1] = rh[3];
                bl[2 * p][0] = rl[0]; bl[2 * p][1] = rl[1];
                bl[2 * p + 1][0] = rl[2]; bl[2 * p + 1][1] = rl[3];
            }
#pragma unroll
            for (int mt = 0; mt < 2; mt++)
#pragma unroll
                for (int nt = 0; nt < 4; nt++) {
                    mma_bf16(acc[mt][nt], ah[mt], bh[nt]);
                    mma_bf16(acc[mt][nt], ah[mt], bl[nt]);
                    mma_bf16(acc[mt][nt], al[mt], bh[nt]);
                }
        }
    };

    // ---------------- pipeline ----------------
    load_A_regs(0);
    cp_B(0, 0);
    store_A(0);
    CP_WAIT0();
    __syncthreads();

    for (int ch = 0; ch < 16; ch++) {
        const int cur = ch & 1;
        if (ch < 15) {
            cp_B(ch + 1, cur ^ 1);
            load_A_regs(ch + 1);
        }
        do_mma(cur);
        if (ch < 15) {
            store_A(cur ^ 1);
            CP_WAIT0();
        }
        __syncthreads();
    }

    // ---------------- epilogue ----------------
#pragma unroll
    for (int mt = 0; mt < 2; mt++) {
        const int row0 = bm + wm + mt * 16 + g;
#pragma unroll
        for (int nt = 0; nt < 4; nt++) {
            const int col = bn + wn + nt * 8 + t * 2;
            const float b0 = __ldg(&bias[col]);
            const float b1 = __ldg(&bias[col + 1]);
            float2 v0 = make_float2(acc[mt][nt][0] + b0, acc[mt][nt][1] + b1);
            float2 v1 = make_float2(acc[mt][nt][2] + b0, acc[mt][nt][3] + b1);
            *(float2*)&C[(size_t)row0 * ldc + col]       = v0;
            *(float2*)&C[(size_t)(row0 + 8) * ldc + col] = v1;
        }
    }
}

struct GArgs {
    const float* A;
    const __nv_bfloat16* Bh;
    const __nv_bfloat16* Bl;
    const float* bias;
    float* C;
};

// Merged Q/K/V projections: grid (128, 1, 3)
__global__ __launch_bounds__(256)
void gemm3_kernel(GArgs p0, GArgs p1, GArgs p2, int ldc)
{
    extern __shared__ __nv_bfloat16 sm[];
    GArgs p = (blockIdx.z == 0) ? p0 : (blockIdx.z == 1) ? p1 : p2;
    gemm_body(p.A, p.Bh, p.Bl, p.bias, p.C, ldc,
              blockIdx.x * 128, blockIdx.y * 64, sm);
}

// Single GEMM: grid (M/128, N/64)
__global__ __launch_bounds__(256)
void gemm1_kernel(GArgs p, int ldc)
{
    extern __shared__ __nv_bfloat16 sm[];
    gemm_body(p.A, p.Bh, p.Bl, p.bias, p.C, ldc,
              blockIdx.x * 128, blockIdx.y * 64, sm);
}

// ---------------------------------------------------------------------------
// Attention middle stage (register-tiled). One CTA per group n, 128 threads.
//   S[i][j] = 0.25 * sum_hh Qp[16n+hh, i] * Kp[16n+hh, j]   (masked)
//   X[n, h*64 + i] = sum_j S[i][j] * Vp[16n+h, j]
// ---------------------------------------------------------------------------
__global__ __launch_bounds__(128)
void attn_kernel(const float* __restrict__ qp, const float* __restrict__ kp,
                 const float* __restrict__ vp, const int* __restrict__ mask,
                 float* __restrict__ X)
{
    __shared__ float Qs[16 * 64];
    __shared__ float Ks[16 * 64];
    __shared__ float Vs[16 * 64];
    __shared__ float S [64 * 64];

    const int n = blockIdx.x, tid = threadIdx.x;
    const float4* qg = (const float4*)(qp + (size_t)n * NHEAD * HEAD);
    const float4* kg = (const float4*)(kp + (size_t)n * NHEAD * HEAD);
    const float4* vg = (const float4*)(vp + (size_t)n * NHEAD * HEAD);
    float4* Qs4 = (float4*)Qs;
    float4* Ks4 = (float4*)Ks;
    float4* Vs4 = (float4*)Vs;

#pragma unroll
    for (int t = tid; t < 256; t += 128) {
        Qs4[t] = qg[t];
        Ks4[t] = kg[t];
        Vs4[t] = vg[t];
    }
    __syncthreads();

    // Stage 1: S = 0.25 * Q^T K (per-thread 4x8 tile)
    const int ti = tid >> 3, tj = tid & 7;
    float acc[4][8];
#pragma unroll
    for (int r = 0; r < 4; r++)
#pragma unroll
        for (int c = 0; c < 8; c++) acc[r][c] = 0.f;

#pragma unroll
    for (int hh = 0; hh < 16; hh++) {
        float4 q  = Qs4[hh * 16 + ti];
        float4 ka = Ks4[hh * 16 + tj * 2];
        float4 kb = Ks4[hh * 16 + tj * 2 + 1];
        float qv[4] = {q.x, q.y, q.z, q.w};
        float kv[8] = {ka.x, ka.y, ka.z, ka.w, kb.x, kb.y, kb.z, kb.w};
#pragma unroll
        for (int r = 0; r < 4; r++)
#pragma unroll
            for (int c = 0; c < 8; c++) acc[r][c] += qv[r] * kv[c];
    }
#pragma unroll
    for (int r = 0; r < 4; r++) {
        int i = ti * 4 + r;
#pragma unroll
        for (int c = 0; c < 8; c++) {
            int j = tj * 8 + c;
            float s = acc[r][c] * 0.25f;
            if (__ldg(&mask[i * 64 + j]) == 0) s = -1e30f;
            S[i * 64 + j] = s;
        }
    }
    __syncthreads();

    // Stage 2: X[i, h] = S[i,:] . V[h,:]  (per-thread 4i x 2h tile)
    const int a = tid >> 3, b = tid & 7;
    const float4* S4 = (const float4*)S;
    float acc2[4][2];
#pragma unroll
    for (int r = 0; r < 4; r++) { acc2[r][0] = 0.f; acc2[r][1] = 0.f; }

#pragma unroll
    for (int j4 = 0; j4 < 16; j4++) {
        float4 v0 = Vs4[(b * 2 + 0) * 16 + j4];
        float4 v1 = Vs4[(b * 2 + 1) * 16 + j4];
#pragma unroll
        for (int r = 0; r < 4; r++) {
            float4 sv = S4[(a * 4 + r) * 16 + j4];
            acc2[r][0] += sv.x * v0.x + sv.y * v0.y + sv.z * v0.z + sv.w * v0.w;
            acc2[r][1] += sv.x * v1.x + sv.y * v1.y + sv.z * v1.z + sv.w * v1.w;
        }
    }

    float* Xn = X + (size_t)n * D_MODEL;
#pragma unroll
    for (int r = 0; r < 4; r++)
#pragma unroll
        for (int c = 0; c < 2; c++)
            Xn[(b * 2 + c) * 64 + a * 4 + r] = acc2[r][c];
}

// ---------------------------------------------------------------------------
extern "C" void kernel_launch(void* const* d_in, const int* in_sizes, int n_in,
                              void* d_out, int out_size)
{
    const float* query = (const float*)d_in[0];
    const float* key   = (const float*)d_in[1];
    const float* value = (const float*)d_in[2];
    const int*   mask  = (const int*)  d_in[3];
    const float* Wq    = (const float*)d_in[4];
    const float* bq    = (const float*)d_in[5];
    const float* Wk    = (const float*)d_in[6];
    const float* bk    = (const float*)d_in[7];
    const float* Wv    = (const float*)d_in[8];
    const float* bv    = (const float*)d_in[9];
    const float* Wp    = (const float*)d_in[10];
    const float* bp    = (const float*)d_in[11];
    float* out = (float*)d_out;

    float *qp, *kp, *vp, *xg;
    cudaGetSymbolAddress((void**)&qp, g_qp);
    cudaGetSymbolAddress((void**)&kp, g_kp);
    cudaGetSymbolAddress((void**)&vp, g_vp);
    cudaGetSymbolAddress((void**)&xg, g_x);
    __nv_bfloat16 *wqh, *wql, *wkh, *wkl, *wvh, *wvl, *wph, *wpl;
    cudaGetSymbolAddress((void**)&wqh, g_wq_h);
    cudaGetSymbolAddress((void**)&wql, g_wq_l);
    cudaGetSymbolAddress((void**)&wkh, g_wk_h);
    cudaGetSymbolAddress((void**)&wkl, g_wk_l);
    cudaGetSymbolAddress((void**)&wvh, g_wv_h);
    cudaGetSymbolAddress((void**)&wvl, g_wv_l);
    cudaGetSymbolAddress((void**)&wph, g_wp_h);
    cudaGetSymbolAddress((void**)&wpl, g_wp_l);

    cudaFuncSetAttribute(gemm3_kernel, cudaFuncAttributeMaxDynamicSharedMemorySize, SM_BYTES);
    cudaFuncSetAttribute(gemm1_kernel, cudaFuncAttributeMaxDynamicSharedMemorySize, SM_BYTES);

    // Weight prep (tiled transpose + bf16 split)
    prep_tr_split_kernel<<<dim3(HEAD / 32, D_MODEL / 32), dim3(32, 8)>>>(Wq, wqh, wql, HEAD);
    prep_tr_split_kernel<<<dim3(HEAD / 32, D_MODEL / 32), dim3(32, 8)>>>(Wk, wkh, wkl, HEAD);
    prep_tr_split_kernel<<<dim3(HEAD / 32, D_MODEL / 32), dim3(32, 8)>>>(Wv, wvh, wvl, HEAD);
    prep_tr_split_kernel<<<dim3(D_MODEL / 32, D_MODEL / 32), dim3(32, 8)>>>(Wp, wph, wpl, D_MODEL);

    // Merged projections: (16384 x 1024) @ (1024 x 64) + bias, x3
    GArgs pq = {query, wqh, wql, bq, qp};
    GArgs pk = {key,   wkh, wkl, bk, kp};
    GArgs pv = {value, wvh, wvl, bv, vp};
    gemm3_kernel<<<dim3(ROWS / 128, 1, 3), 256, SM_BYTES>>>(pq, pk, pv, HEAD);

    // Attention middle stage -> X (1024 x 1024)
    attn_kernel<<<NGRP, 128>>>(qp, kp, vp, mask, xg);

    // Output projection: (1024 x 1024) @ (1024 x 1024) + bias
    GArgs pp = {xg, wph, wpl, bp, out};
    gemm1_kernel<<<dim3(NGRP / 128, D_MODEL / 64), 256, SM_BYTES>>>(pp, D_MODEL);
}